// round 5
// baseline (speedup 1.0000x reference)
#include <cuda_runtime.h>
#include <math.h>

#define BATCH 16
#define CHAN  256
#define NPIX  4096

typedef unsigned long long ull;

__device__ float g_energy[3u * BATCH * CHAN * CHAN];
__device__ float g_attn[(unsigned)BATCH * CHAN * CHAN];
__device__ float g_M[(unsigned)BATCH * CHAN * CHAN];

// ---- packed f32x2 helpers ---------------------------------------------------
__device__ __forceinline__ ull bcast2(float v) {
    ull r;
    asm("mov.b64 %0, {%1, %1};" : "=l"(r) : "f"(v));
    return r;
}
__device__ __forceinline__ void fma2(ull& d, ull a, ull b) {
    asm("fma.rn.f32x2 %0, %1, %2, %0;" : "+l"(d) : "l"(a), "l"(b));
}
__device__ __forceinline__ float2 unpack2(ull v) {
    float2 r;
    asm("mov.b64 {%0, %1}, %2;" : "=f"(r.x), "=f"(r.y) : "l"(v));
    return r;
}

// ---------------------------------------------------------------------------
// Kernel 1: energy[s][b][c][d] = sum_n x[b,c,n] * src_s[b,d,n]   (NT GEMM)
// Block tile 128x128x16, 256 threads, 8x8 micro-tile (rows {ty*4, 64+ty*4},
// cols {tx*4, 64+tx*4}).  2.0 FLOP per LDS byte (crossbar/FMA balanced).
// ---------------------------------------------------------------------------
__global__ __launch_bounds__(256, 2)
void energy_kernel(const float* __restrict__ x, const float* __restrict__ y,
                   const float* __restrict__ z)
{
    constexpr int TK = 16, PA = 136;
    __shared__ float As[TK * PA];
    __shared__ float Bs[TK * PA];

    int id = blockIdx.x;
    int t  = id & 3;            // 2x2 tiles of 128
    int bs = id >> 2;
    int b  = bs & 15;
    int s  = bs >> 4;
    int cBase = (t >> 1) * 128;
    int dBase = (t & 1) * 128;

    const float* A = x + (size_t)b * (CHAN * NPIX);
    const float* S = (s == 0 ? x : (s == 1 ? y : z)) + (size_t)b * (CHAN * NPIX);

    int tid = threadIdx.x;
    int ty = tid >> 4, tx = tid & 15;

    int mld = tid >> 2;          // 0..63
    int kc  = (tid & 3) * 4;     // 0,4,8,12

    const float* pA0 = A + (size_t)(cBase + mld) * NPIX + kc;
    const float* pA1 = pA0 + (size_t)64 * NPIX;
    const float* pB0 = S + (size_t)(dBase + mld) * NPIX + kc;
    const float* pB1 = pB0 + (size_t)64 * NPIX;

    float4 ra0 = *(const float4*)pA0;
    float4 ra1 = *(const float4*)pA1;
    float4 rb0 = *(const float4*)pB0;
    float4 rb1 = *(const float4*)pB1;

    // acc2[i][np]: row i (i<4 -> ty*4+i, else 64+ty*4+i-4) x packed col-pair np
    ull acc2[8][4];
    #pragma unroll
    for (int i = 0; i < 8; i++)
        #pragma unroll
        for (int j = 0; j < 4; j++) acc2[i][j] = 0ull;

    for (int kb = 0; kb < NPIX; kb += TK) {
        As[(kc+0)*PA + mld] = ra0.x;
        As[(kc+1)*PA + mld] = ra0.y;
        As[(kc+2)*PA + mld] = ra0.z;
        As[(kc+3)*PA + mld] = ra0.w;
        As[(kc+0)*PA + 64 + mld] = ra1.x;
        As[(kc+1)*PA + 64 + mld] = ra1.y;
        As[(kc+2)*PA + 64 + mld] = ra1.z;
        As[(kc+3)*PA + 64 + mld] = ra1.w;
        Bs[(kc+0)*PA + mld] = rb0.x;
        Bs[(kc+1)*PA + mld] = rb0.y;
        Bs[(kc+2)*PA + mld] = rb0.z;
        Bs[(kc+3)*PA + mld] = rb0.w;
        Bs[(kc+0)*PA + 64 + mld] = rb1.x;
        Bs[(kc+1)*PA + 64 + mld] = rb1.y;
        Bs[(kc+2)*PA + 64 + mld] = rb1.z;
        Bs[(kc+3)*PA + 64 + mld] = rb1.w;
        __syncthreads();

        if (kb + TK < NPIX) {
            pA0 += TK; pA1 += TK; pB0 += TK; pB1 += TK;
            ra0 = *(const float4*)pA0;
            ra1 = *(const float4*)pA1;
            rb0 = *(const float4*)pB0;
            rb1 = *(const float4*)pB1;
        }

        #pragma unroll
        for (int k = 0; k < TK; k++) {
            float4 a0 = *(const float4*)&As[k*PA + ty*4];
            float4 a1 = *(const float4*)&As[k*PA + 64 + ty*4];
            ull aa[8] = {bcast2(a0.x), bcast2(a0.y), bcast2(a0.z), bcast2(a0.w),
                         bcast2(a1.x), bcast2(a1.y), bcast2(a1.z), bcast2(a1.w)};
            ulonglong2 bq0 = *(const ulonglong2*)&Bs[k*PA + tx*4];
            ulonglong2 bq1 = *(const ulonglong2*)&Bs[k*PA + 64 + tx*4];
            ull bp[4] = {bq0.x, bq0.y, bq1.x, bq1.y};
            #pragma unroll
            for (int i = 0; i < 8; i++)
                #pragma unroll
                for (int j = 0; j < 4; j++)
                    fma2(acc2[i][j], aa[i], bp[j]);
        }
        __syncthreads();
    }

    float* E = g_energy + ((size_t)s * BATCH + b) * (CHAN * CHAN);
    #pragma unroll
    for (int i = 0; i < 8; i++) {
        int row = cBase + ((i < 4) ? (ty*4 + i) : (64 + ty*4 + i - 4));
        float2 c0 = unpack2(acc2[i][0]);
        float2 c1 = unpack2(acc2[i][1]);
        float2 c2 = unpack2(acc2[i][2]);
        float2 c3 = unpack2(acc2[i][3]);
        *(float4*)&E[(size_t)row * CHAN + dBase + tx*4] =
            make_float4(c0.x, c0.y, c1.x, c1.y);
        *(float4*)&E[(size_t)row * CHAN + dBase + 64 + tx*4] =
            make_float4(c2.x, c2.y, c3.x, c3.y);
    }
}

// ---------------------------------------------------------------------------
// Kernel 2: attn[b][c][:] = sum_s softmax(rowmax(E_s) - E_s); one warp/row.
// ---------------------------------------------------------------------------
__global__ __launch_bounds__(256)
void softmax_sum_kernel()
{
    int gwarp = (blockIdx.x * blockDim.x + threadIdx.x) >> 5;
    int lane  = threadIdx.x & 31;

    float acc[8];
    #pragma unroll
    for (int i = 0; i < 8; i++) acc[i] = 0.f;

    #pragma unroll
    for (int s = 0; s < 3; s++) {
        const float* row = g_energy + ((size_t)s * BATCH * CHAN + gwarp) * CHAN;
        float4 e0 = *(const float4*)&row[lane * 8];
        float4 e1 = *(const float4*)&row[lane * 8 + 4];
        float e[8] = {e0.x, e0.y, e0.z, e0.w, e1.x, e1.y, e1.z, e1.w};

        float m1 = e[0];
        #pragma unroll
        for (int i = 1; i < 8; i++) m1 = fmaxf(m1, e[i]);
        #pragma unroll
        for (int o = 16; o > 0; o >>= 1)
            m1 = fmaxf(m1, __shfl_xor_sync(0xffffffffu, m1, o));

        float v[8], m2 = -3.402823466e38f;
        #pragma unroll
        for (int i = 0; i < 8; i++) { v[i] = m1 - e[i]; m2 = fmaxf(m2, v[i]); }
        #pragma unroll
        for (int o = 16; o > 0; o >>= 1)
            m2 = fmaxf(m2, __shfl_xor_sync(0xffffffffu, m2, o));

        float p[8], Ssum = 0.f;
        #pragma unroll
        for (int i = 0; i < 8; i++) { p[i] = expf(v[i] - m2); Ssum += p[i]; }
        #pragma unroll
        for (int o = 16; o > 0; o >>= 1)
            Ssum += __shfl_xor_sync(0xffffffffu, Ssum, o);

        float inv = 1.f / Ssum;
        #pragma unroll
        for (int i = 0; i < 8; i++) acc[i] += p[i] * inv;
    }

    float* out = g_attn + (size_t)gwarp * CHAN + lane * 8;
    *(float4*)&out[0] = make_float4(acc[0], acc[1], acc[2], acc[3]);
    *(float4*)&out[4] = make_float4(acc[4], acc[5], acc[6], acc[7]);
}

// ---------------------------------------------------------------------------
// Kernels 3/4: TN GEMM, C = A @ B, K=256. Block tile 128x128x16, 8x8 micro.
//   FINAL=false: O = gamma * acc
//   FINAL=true : O = acc + gamma*bias[m] + resid
// ---------------------------------------------------------------------------
template<int NCOLS, bool FINAL>
__global__ __launch_bounds__(256, 2)
void gemm_tn(const float* __restrict__ Ab, long aStride,
             const float* __restrict__ Bb, long bStride,
             float* __restrict__ Ob,
             const float* __restrict__ bias,
             const float* __restrict__ gamma_p,
             const float* __restrict__ resid)
{
    constexpr int TK = 16, Kdim = 256, PA = 136;
    constexpr int NT = NCOLS / 128;
    __shared__ float As[TK * PA];
    __shared__ float Bs[TK * 128];

    int id = blockIdx.x;
    int nt = id % NT; id /= NT;
    int mt = id & 1;
    int b  = id >> 1;
    int mBase = mt * 128, nBase = nt * 128;

    const float* A = Ab + (size_t)b * aStride;
    const float* B = Bb + (size_t)b * bStride;
    float* O = Ob + (size_t)b * ((size_t)CHAN * NCOLS);
    const float* R = FINAL ? (resid + (size_t)b * ((size_t)CHAN * NCOLS)) : nullptr;

    int tid = threadIdx.x;
    int ty = tid >> 4, tx = tid & 15;

    int mldA = tid >> 2, kcA = (tid & 3) * 4;   // A: 2 float4 / thread
    int krB = tid >> 5, nvB = tid & 31;         // B: 2 float4 / thread

    const float* pA0 = A + (size_t)(mBase + mldA) * Kdim + kcA;
    const float* pA1 = pA0 + (size_t)64 * Kdim;
    const float* pB0 = B + (size_t)krB * NCOLS + nBase + nvB * 4;
    const float* pB1 = pB0 + (size_t)8 * NCOLS;

    float4 ra0 = *(const float4*)pA0;
    float4 ra1 = *(const float4*)pA1;
    float4 rb0 = *(const float4*)pB0;
    float4 rb1 = *(const float4*)pB1;

    ull acc2[8][4];
    #pragma unroll
    for (int i = 0; i < 8; i++)
        #pragma unroll
        for (int j = 0; j < 4; j++) acc2[i][j] = 0ull;

    for (int kb = 0; kb < Kdim; kb += TK) {
        As[(kcA+0)*PA + mldA] = ra0.x;
        As[(kcA+1)*PA + mldA] = ra0.y;
        As[(kcA+2)*PA + mldA] = ra0.z;
        As[(kcA+3)*PA + mldA] = ra0.w;
        As[(kcA+0)*PA + 64 + mldA] = ra1.x;
        As[(kcA+1)*PA + 64 + mldA] = ra1.y;
        As[(kcA+2)*PA + 64 + mldA] = ra1.z;
        As[(kcA+3)*PA + 64 + mldA] = ra1.w;
        *(float4*)&Bs[krB * 128 + nvB * 4]       = rb0;
        *(float4*)&Bs[(krB + 8) * 128 + nvB * 4] = rb1;
        __syncthreads();

        if (kb + TK < Kdim) {
            pA0 += TK; pA1 += TK;
            pB0 += (size_t)TK * NCOLS; pB1 += (size_t)TK * NCOLS;
            ra0 = *(const float4*)pA0;
            ra1 = *(const float4*)pA1;
            rb0 = *(const float4*)pB0;
            rb1 = *(const float4*)pB1;
        }

        #pragma unroll
        for (int k = 0; k < TK; k++) {
            float4 a0 = *(const float4*)&As[k*PA + ty*4];
            float4 a1 = *(const float4*)&As[k*PA + 64 + ty*4];
            ull aa[8] = {bcast2(a0.x), bcast2(a0.y), bcast2(a0.z), bcast2(a0.w),
                         bcast2(a1.x), bcast2(a1.y), bcast2(a1.z), bcast2(a1.w)};
            ulonglong2 bq0 = *(const ulonglong2*)&Bs[k*128 + tx*4];
            ulonglong2 bq1 = *(const ulonglong2*)&Bs[k*128 + 64 + tx*4];
            ull bp[4] = {bq0.x, bq0.y, bq1.x, bq1.y};
            #pragma unroll
            for (int i = 0; i < 8; i++)
                #pragma unroll
                for (int j = 0; j < 4; j++)
                    fma2(acc2[i][j], aa[i], bp[j]);
        }
        __syncthreads();
    }

    float gamma = gamma_p[0];
    #pragma unroll
    for (int i = 0; i < 8; i++) {
        int row = mBase + ((i < 4) ? (ty*4 + i) : (64 + ty*4 + i - 4));
        size_t base = (size_t)row * NCOLS + nBase + tx*4;
        float2 c0 = unpack2(acc2[i][0]);
        float2 c1 = unpack2(acc2[i][1]);
        float2 c2 = unpack2(acc2[i][2]);
        float2 c3 = unpack2(acc2[i][3]);
        if (FINAL) {
            float gb = gamma * bias[row];
            float4 r0 = *(const float4*)&R[base];
            float4 r1 = *(const float4*)&R[base + 64];
            *(float4*)&O[base] = make_float4(
                c0.x + gb + r0.x, c0.y + gb + r0.y,
                c1.x + gb + r0.z, c1.y + gb + r0.w);
            *(float4*)&O[base + 64] = make_float4(
                c2.x + gb + r1.x, c2.y + gb + r1.y,
                c3.x + gb + r1.z, c3.y + gb + r1.w);
        } else {
            *(float4*)&O[base] = make_float4(
                gamma*c0.x, gamma*c0.y, gamma*c1.x, gamma*c1.y);
            *(float4*)&O[base + 64] = make_float4(
                gamma*c2.x, gamma*c2.y, gamma*c3.x, gamma*c3.y);
        }
    }
}

// ---------------------------------------------------------------------------
extern "C" void kernel_launch(void* const* d_in, const int* in_sizes, int n_in,
                              void* d_out, int out_size)
{
    const float* x      = (const float*)d_in[0];
    const float* y      = (const float*)d_in[1];
    const float* z      = (const float*)d_in[2];
    const float* conv_w = (const float*)d_in[3];
    const float* conv_b = (const float*)d_in[4];
    const float* gamma  = (const float*)d_in[5];
    float* out = (float*)d_out;

    float *pAttn, *pM;
    cudaGetSymbolAddress((void**)&pAttn, g_attn);
    cudaGetSymbolAddress((void**)&pM, g_M);

    // 1) three energy GEMMs: 3*16*4 = 192 CTAs (single wave at occ 2)
    energy_kernel<<<3 * BATCH * 4, 256>>>(x, y, z);
    // 2) softmax + sum over sources
    softmax_sum_kernel<<<BATCH * CHAN / 8, 256>>>();
    // 3) M_b = gamma * conv_w @ attn_b  (64 CTAs)
    gemm_tn<CHAN, false><<<BATCH * 2 * 2, 256>>>(
        conv_w, 0, pAttn, (long)CHAN * CHAN, pM, nullptr, gamma, nullptr);
    // 4) out = M_b @ x_b + gamma*conv_b + x  (1024 CTAs)
    gemm_tn<NPIX, true><<<BATCH * 2 * 32, 256>>>(
        pM, (long)CHAN * CHAN, x, (long)CHAN * NPIX, out, conv_b, gamma, x);
}

// round 6
// speedup vs baseline: 1.2610x; 1.2610x over previous
#include <cuda_runtime.h>
#include <math.h>

#define BATCH 16
#define CHAN  256
#define NPIX  4096
#define KSPLIT 4
#define KCH   (NPIX / KSPLIT)   // 1024

typedef unsigned long long ull;

// Scratch (allocation-free: __device__ globals)
__device__ float g_epart[(size_t)KSPLIT * 3 * BATCH * CHAN * CHAN];  // 50.3 MB
__device__ float g_attn[(unsigned)BATCH * CHAN * CHAN];
__device__ float g_M[(unsigned)BATCH * CHAN * CHAN];

// ---- packed f32x2 helpers ---------------------------------------------------
__device__ __forceinline__ ull bcast2(float v) {
    ull r;
    asm("mov.b64 %0, {%1, %1};" : "=l"(r) : "f"(v));
    return r;
}
__device__ __forceinline__ void fma2(ull& d, ull a, ull b) {
    asm("fma.rn.f32x2 %0, %1, %2, %0;" : "+l"(d) : "l"(a), "l"(b));
}
__device__ __forceinline__ float2 unpack2(ull v) {
    float2 r;
    asm("mov.b64 {%0, %1}, %2;" : "=f"(r.x), "=f"(r.y) : "l"(v));
    return r;
}

// ---------------------------------------------------------------------------
// Kernel 1: partial energy, split-K.
//   g_epart[kc][s][b][c][d] = sum_{n in chunk kc} x[b,c,n] * src_s[b,d,n]
// Block tile 128x128x16, 256 threads, 8x8 micro-tile, 768 CTAs.
// ---------------------------------------------------------------------------
__global__ __launch_bounds__(256, 2)
void energy_kernel(const float* __restrict__ x, const float* __restrict__ y,
                   const float* __restrict__ z)
{
    constexpr int TK = 16, PA = 136;
    __shared__ float As[TK * PA];
    __shared__ float Bs[TK * PA];

    int id = blockIdx.x;
    int t      = id & 3;         // 2x2 tiles of 128 (fastest: L2 reuse)
    int kchunk = (id >> 2) & 3;
    int bs     = id >> 4;
    int b  = bs & 15;
    int s  = bs >> 4;
    int cBase = (t >> 1) * 128;
    int dBase = (t & 1) * 128;
    int kStart = kchunk * KCH;

    const float* A = x + (size_t)b * (CHAN * NPIX);
    const float* S = (s == 0 ? x : (s == 1 ? y : z)) + (size_t)b * (CHAN * NPIX);

    int tid = threadIdx.x;
    int ty = tid >> 4, tx = tid & 15;

    int mld = tid >> 2;          // 0..63
    int kc  = (tid & 3) * 4;     // 0,4,8,12

    const float* pA0 = A + (size_t)(cBase + mld) * NPIX + kStart + kc;
    const float* pA1 = pA0 + (size_t)64 * NPIX;
    const float* pB0 = S + (size_t)(dBase + mld) * NPIX + kStart + kc;
    const float* pB1 = pB0 + (size_t)64 * NPIX;

    float4 ra0 = *(const float4*)pA0;
    float4 ra1 = *(const float4*)pA1;
    float4 rb0 = *(const float4*)pB0;
    float4 rb1 = *(const float4*)pB1;

    ull acc2[8][4];
    #pragma unroll
    for (int i = 0; i < 8; i++)
        #pragma unroll
        for (int j = 0; j < 4; j++) acc2[i][j] = 0ull;

    for (int kb = 0; kb < KCH; kb += TK) {
        As[(kc+0)*PA + mld] = ra0.x;
        As[(kc+1)*PA + mld] = ra0.y;
        As[(kc+2)*PA + mld] = ra0.z;
        As[(kc+3)*PA + mld] = ra0.w;
        As[(kc+0)*PA + 64 + mld] = ra1.x;
        As[(kc+1)*PA + 64 + mld] = ra1.y;
        As[(kc+2)*PA + 64 + mld] = ra1.z;
        As[(kc+3)*PA + 64 + mld] = ra1.w;
        Bs[(kc+0)*PA + mld] = rb0.x;
        Bs[(kc+1)*PA + mld] = rb0.y;
        Bs[(kc+2)*PA + mld] = rb0.z;
        Bs[(kc+3)*PA + mld] = rb0.w;
        Bs[(kc+0)*PA + 64 + mld] = rb1.x;
        Bs[(kc+1)*PA + 64 + mld] = rb1.y;
        Bs[(kc+2)*PA + 64 + mld] = rb1.z;
        Bs[(kc+3)*PA + 64 + mld] = rb1.w;
        __syncthreads();

        if (kb + TK < KCH) {
            pA0 += TK; pA1 += TK; pB0 += TK; pB1 += TK;
            ra0 = *(const float4*)pA0;
            ra1 = *(const float4*)pA1;
            rb0 = *(const float4*)pB0;
            rb1 = *(const float4*)pB1;
        }

        #pragma unroll
        for (int k = 0; k < TK; k++) {
            float4 a0 = *(const float4*)&As[k*PA + ty*4];
            float4 a1 = *(const float4*)&As[k*PA + 64 + ty*4];
            ull aa[8] = {bcast2(a0.x), bcast2(a0.y), bcast2(a0.z), bcast2(a0.w),
                         bcast2(a1.x), bcast2(a1.y), bcast2(a1.z), bcast2(a1.w)};
            ulonglong2 bq0 = *(const ulonglong2*)&Bs[k*PA + tx*4];
            ulonglong2 bq1 = *(const ulonglong2*)&Bs[k*PA + 64 + tx*4];
            ull bp[4] = {bq0.x, bq0.y, bq1.x, bq1.y};
            #pragma unroll
            for (int i = 0; i < 8; i++)
                #pragma unroll
                for (int j = 0; j < 4; j++)
                    fma2(acc2[i][j], aa[i], bp[j]);
        }
        __syncthreads();
    }

    float* E = g_epart + (((size_t)kchunk * 3 + s) * BATCH + b) * (CHAN * CHAN);
    #pragma unroll
    for (int i = 0; i < 8; i++) {
        int row = cBase + ((i < 4) ? (ty*4 + i) : (64 + ty*4 + i - 4));
        float2 c0 = unpack2(acc2[i][0]);
        float2 c1 = unpack2(acc2[i][1]);
        float2 c2 = unpack2(acc2[i][2]);
        float2 c3 = unpack2(acc2[i][3]);
        *(float4*)&E[(size_t)row * CHAN + dBase + tx*4] =
            make_float4(c0.x, c0.y, c1.x, c1.y);
        *(float4*)&E[(size_t)row * CHAN + dBase + 64 + tx*4] =
            make_float4(c2.x, c2.y, c3.x, c3.y);
    }
}

// ---------------------------------------------------------------------------
// Kernel 2: attn[b][c][:] = sum_s softmax(rowmax(E_s) - E_s), where
// E_s = sum over KSPLIT partials. One warp per (b,c) row.
// ---------------------------------------------------------------------------
__global__ __launch_bounds__(256)
void softmax_sum_kernel()
{
    int gwarp = (blockIdx.x * blockDim.x + threadIdx.x) >> 5;  // row = b*CHAN+c
    int lane  = threadIdx.x & 31;

    float acc[8];
    #pragma unroll
    for (int i = 0; i < 8; i++) acc[i] = 0.f;

    #pragma unroll
    for (int s = 0; s < 3; s++) {
        float e[8];
        #pragma unroll
        for (int i = 0; i < 8; i++) e[i] = 0.f;
        #pragma unroll
        for (int p = 0; p < KSPLIT; p++) {
            const float* row = g_epart +
                (((size_t)p * 3 + s) * BATCH * CHAN + gwarp) * CHAN;
            float4 e0 = *(const float4*)&row[lane * 8];
            float4 e1 = *(const float4*)&row[lane * 8 + 4];
            e[0] += e0.x; e[1] += e0.y; e[2] += e0.z; e[3] += e0.w;
            e[4] += e1.x; e[5] += e1.y; e[6] += e1.z; e[7] += e1.w;
        }

        float m1 = e[0];
        #pragma unroll
        for (int i = 1; i < 8; i++) m1 = fmaxf(m1, e[i]);
        #pragma unroll
        for (int o = 16; o > 0; o >>= 1)
            m1 = fmaxf(m1, __shfl_xor_sync(0xffffffffu, m1, o));

        float v[8], m2 = -3.402823466e38f;
        #pragma unroll
        for (int i = 0; i < 8; i++) { v[i] = m1 - e[i]; m2 = fmaxf(m2, v[i]); }
        #pragma unroll
        for (int o = 16; o > 0; o >>= 1)
            m2 = fmaxf(m2, __shfl_xor_sync(0xffffffffu, m2, o));

        float p8[8], Ssum = 0.f;
        #pragma unroll
        for (int i = 0; i < 8; i++) { p8[i] = expf(v[i] - m2); Ssum += p8[i]; }
        #pragma unroll
        for (int o = 16; o > 0; o >>= 1)
            Ssum += __shfl_xor_sync(0xffffffffu, Ssum, o);

        float inv = 1.f / Ssum;
        #pragma unroll
        for (int i = 0; i < 8; i++) acc[i] += p8[i] * inv;
    }

    float* out = g_attn + (size_t)gwarp * CHAN + lane * 8;
    *(float4*)&out[0] = make_float4(acc[0], acc[1], acc[2], acc[3]);
    *(float4*)&out[4] = make_float4(acc[4], acc[5], acc[6], acc[7]);
}

// ---------------------------------------------------------------------------
// Kernels 3/4: TN GEMM, C = A @ B, K=256. Block tile 128x128x16, 8x8 micro.
//   FINAL=false: O = gamma * acc
//   FINAL=true : O = acc + gamma*bias[m] + resid
// ---------------------------------------------------------------------------
template<int NCOLS, bool FINAL>
__global__ __launch_bounds__(256, 2)
void gemm_tn(const float* __restrict__ Ab, long aStride,
             const float* __restrict__ Bb, long bStride,
             float* __restrict__ Ob,
             const float* __restrict__ bias,
             const float* __restrict__ gamma_p,
             const float* __restrict__ resid)
{
    constexpr int TK = 16, Kdim = 256, PA = 136;
    constexpr int NT = NCOLS / 128;
    __shared__ float As[TK * PA];
    __shared__ float Bs[TK * 128];

    int id = blockIdx.x;
    int nt = id % NT; id /= NT;
    int mt = id & 1;
    int b  = id >> 1;
    int mBase = mt * 128, nBase = nt * 128;

    const float* A = Ab + (size_t)b * aStride;
    const float* B = Bb + (size_t)b * bStride;
    float* O = Ob + (size_t)b * ((size_t)CHAN * NCOLS);
    const float* R = FINAL ? (resid + (size_t)b * ((size_t)CHAN * NCOLS)) : nullptr;

    int tid = threadIdx.x;
    int ty = tid >> 4, tx = tid & 15;

    int mldA = tid >> 2, kcA = (tid & 3) * 4;
    int krB = tid >> 5, nvB = tid & 31;

    const float* pA0 = A + (size_t)(mBase + mldA) * Kdim + kcA;
    const float* pA1 = pA0 + (size_t)64 * Kdim;
    const float* pB0 = B + (size_t)krB * NCOLS + nBase + nvB * 4;
    const float* pB1 = pB0 + (size_t)8 * NCOLS;

    float4 ra0 = *(const float4*)pA0;
    float4 ra1 = *(const float4*)pA1;
    float4 rb0 = *(const float4*)pB0;
    float4 rb1 = *(const float4*)pB1;

    ull acc2[8][4];
    #pragma unroll
    for (int i = 0; i < 8; i++)
        #pragma unroll
        for (int j = 0; j < 4; j++) acc2[i][j] = 0ull;

    for (int kb = 0; kb < Kdim; kb += TK) {
        As[(kcA+0)*PA + mldA] = ra0.x;
        As[(kcA+1)*PA + mldA] = ra0.y;
        As[(kcA+2)*PA + mldA] = ra0.z;
        As[(kcA+3)*PA + mldA] = ra0.w;
        As[(kcA+0)*PA + 64 + mldA] = ra1.x;
        As[(kcA+1)*PA + 64 + mldA] = ra1.y;
        As[(kcA+2)*PA + 64 + mldA] = ra1.z;
        As[(kcA+3)*PA + 64 + mldA] = ra1.w;
        *(float4*)&Bs[krB * 128 + nvB * 4]       = rb0;
        *(float4*)&Bs[(krB + 8) * 128 + nvB * 4] = rb1;
        __syncthreads();

        if (kb + TK < Kdim) {
            pA0 += TK; pA1 += TK;
            pB0 += (size_t)TK * NCOLS; pB1 += (size_t)TK * NCOLS;
            ra0 = *(const float4*)pA0;
            ra1 = *(const float4*)pA1;
            rb0 = *(const float4*)pB0;
            rb1 = *(const float4*)pB1;
        }

        #pragma unroll
        for (int k = 0; k < TK; k++) {
            float4 a0 = *(const float4*)&As[k*PA + ty*4];
            float4 a1 = *(const float4*)&As[k*PA + 64 + ty*4];
            ull aa[8] = {bcast2(a0.x), bcast2(a0.y), bcast2(a0.z), bcast2(a0.w),
                         bcast2(a1.x), bcast2(a1.y), bcast2(a1.z), bcast2(a1.w)};
            ulonglong2 bq0 = *(const ulonglong2*)&Bs[k*128 + tx*4];
            ulonglong2 bq1 = *(const ulonglong2*)&Bs[k*128 + 64 + tx*4];
            ull bp[4] = {bq0.x, bq0.y, bq1.x, bq1.y};
            #pragma unroll
            for (int i = 0; i < 8; i++)
                #pragma unroll
                for (int j = 0; j < 4; j++)
                    fma2(acc2[i][j], aa[i], bp[j]);
        }
        __syncthreads();
    }

    float gamma = gamma_p[0];
    #pragma unroll
    for (int i = 0; i < 8; i++) {
        int row = mBase + ((i < 4) ? (ty*4 + i) : (64 + ty*4 + i - 4));
        size_t base = (size_t)row * NCOLS + nBase + tx*4;
        float2 c0 = unpack2(acc2[i][0]);
        float2 c1 = unpack2(acc2[i][1]);
        float2 c2 = unpack2(acc2[i][2]);
        float2 c3 = unpack2(acc2[i][3]);
        if (FINAL) {
            float gb = gamma * bias[row];
            float4 r0 = *(const float4*)&R[base];
            float4 r1 = *(const float4*)&R[base + 64];
            *(float4*)&O[base] = make_float4(
                c0.x + gb + r0.x, c0.y + gb + r0.y,
                c1.x + gb + r0.z, c1.y + gb + r0.w);
            *(float4*)&O[base + 64] = make_float4(
                c2.x + gb + r1.x, c2.y + gb + r1.y,
                c3.x + gb + r1.z, c3.y + gb + r1.w);
        } else {
            *(float4*)&O[base] = make_float4(
                gamma*c0.x, gamma*c0.y, gamma*c1.x, gamma*c1.y);
            *(float4*)&O[base + 64] = make_float4(
                gamma*c2.x, gamma*c2.y, gamma*c3.x, gamma*c3.y);
        }
    }
}

// ---------------------------------------------------------------------------
extern "C" void kernel_launch(void* const* d_in, const int* in_sizes, int n_in,
                              void* d_out, int out_size)
{
    const float* x      = (const float*)d_in[0];
    const float* y      = (const float*)d_in[1];
    const float* z      = (const float*)d_in[2];
    const float* conv_w = (const float*)d_in[3];
    const float* conv_b = (const float*)d_in[4];
    const float* gamma  = (const float*)d_in[5];
    float* out = (float*)d_out;

    float *pAttn, *pM;
    cudaGetSymbolAddress((void**)&pAttn, g_attn);
    cudaGetSymbolAddress((void**)&pM, g_M);

    // 1) three energy GEMMs, split-K=4: 3*16*4*4 = 768 CTAs
    energy_kernel<<<3 * BATCH * 4 * KSPLIT, 256>>>(x, y, z);
    // 2) sum partials + softmax + sum over sources
    softmax_sum_kernel<<<BATCH * CHAN / 8, 256>>>();
    // 3) M_b = gamma * conv_w @ attn_b  (64 CTAs)
    gemm_tn<CHAN, false><<<BATCH * 2 * 2, 256>>>(
        conv_w, 0, pAttn, (long)CHAN * CHAN, pM, nullptr, gamma, nullptr);
    // 4) out = M_b @ x_b + gamma*conv_b + x  (1024 CTAs)
    gemm_tn<NPIX, true><<<BATCH * 2 * 32, 256>>>(
        pM, (long)CHAN * CHAN, x, (long)CHAN * NPIX, out, conv_b, gamma, x);
}

// round 12
// speedup vs baseline: 1.2991x; 1.0303x over previous
#include <cuda_runtime.h>
#include <math.h>
#include <stdint.h>

#define BATCH 16
#define CHAN  256
#define NPIX  4096
#define KSPLIT 4
#define KCH   (NPIX / KSPLIT)   // 1024

typedef unsigned long long ull;

// Scratch (allocation-free: __device__ globals)
__device__ float g_epart[(size_t)KSPLIT * 3 * BATCH * CHAN * CHAN];  // 50.3 MB
__device__ float g_attn[(unsigned)BATCH * CHAN * CHAN];
__device__ float g_M[(unsigned)BATCH * CHAN * CHAN];

// ---- packed f32x2 helpers ---------------------------------------------------
__device__ __forceinline__ ull bcast2(float v) {
    ull r; asm("mov.b64 %0, {%1, %1};" : "=l"(r) : "f"(v)); return r;
}
__device__ __forceinline__ void fma2(ull& d, ull a, ull b) {
    asm("fma.rn.f32x2 %0, %1, %2, %0;" : "+l"(d) : "l"(a), "l"(b));
}
__device__ __forceinline__ float2 unpack2(ull v) {
    float2 r; asm("mov.b64 {%0, %1}, %2;" : "=f"(r.x), "=f"(r.y) : "l"(v)); return r;
}

// ---------------------------------------------------------------------------
// Kernel 1: partial energy, split-K=4, double-buffered smem (1 sync/iter).
//   g_epart[kc][s][b][c][d] = sum_{n in chunk kc} x[b,c,n] * src_s[b,d,n]
// Block tile 128x128x16, 256 threads, 8x8 micro-tile, 768 CTAs.
// ---------------------------------------------------------------------------
__global__ __launch_bounds__(256, 2)
void energy_kernel(const float* __restrict__ x, const float* __restrict__ y,
                   const float* __restrict__ z)
{
    constexpr int TK = 16, PA = 136;
    constexpr int NIT = KCH / TK;     // 64
    __shared__ float As[2][TK * PA];
    __shared__ float Bs[2][TK * PA];

    int id = blockIdx.x;
    int t      = id & 3;
    int kchunk = (id >> 2) & 3;
    int bs     = id >> 4;
    int b  = bs & 15;
    int s  = bs >> 4;
    int cBase = (t >> 1) * 128;
    int dBase = (t & 1) * 128;
    int kStart = kchunk * KCH;

    const float* A = x + (size_t)b * (CHAN * NPIX);
    const float* S = (s == 0 ? x : (s == 1 ? y : z)) + (size_t)b * (CHAN * NPIX);

    int tid = threadIdx.x;
    int ty = tid >> 4, tx = tid & 15;

    int mld = tid >> 2;          // 0..63
    int kc  = (tid & 3) * 4;     // 0,4,8,12

    const float* pA0 = A + (size_t)(cBase + mld) * NPIX + kStart + kc;
    const float* pA1 = pA0 + (size_t)64 * NPIX;
    const float* pB0 = S + (size_t)(dBase + mld) * NPIX + kStart + kc;
    const float* pB1 = pB0 + (size_t)64 * NPIX;

    float4 ra0, ra1, rb0, rb1;

    // prologue: chunk 0 -> buf 0
    ra0 = *(const float4*)pA0;  ra1 = *(const float4*)pA1;
    rb0 = *(const float4*)pB0;  rb1 = *(const float4*)pB1;
    {
        float* a = As[0]; float* bsm = Bs[0];
        a[(kc+0)*PA + mld] = ra0.x;  a[(kc+1)*PA + mld] = ra0.y;
        a[(kc+2)*PA + mld] = ra0.z;  a[(kc+3)*PA + mld] = ra0.w;
        a[(kc+0)*PA + 64 + mld] = ra1.x;  a[(kc+1)*PA + 64 + mld] = ra1.y;
        a[(kc+2)*PA + 64 + mld] = ra1.z;  a[(kc+3)*PA + 64 + mld] = ra1.w;
        bsm[(kc+0)*PA + mld] = rb0.x;  bsm[(kc+1)*PA + mld] = rb0.y;
        bsm[(kc+2)*PA + mld] = rb0.z;  bsm[(kc+3)*PA + mld] = rb0.w;
        bsm[(kc+0)*PA + 64 + mld] = rb1.x;  bsm[(kc+1)*PA + 64 + mld] = rb1.y;
        bsm[(kc+2)*PA + 64 + mld] = rb1.z;  bsm[(kc+3)*PA + 64 + mld] = rb1.w;
    }
    // prefetch chunk 1
    pA0 += TK; pA1 += TK; pB0 += TK; pB1 += TK;
    ra0 = *(const float4*)pA0;  ra1 = *(const float4*)pA1;
    rb0 = *(const float4*)pB0;  rb1 = *(const float4*)pB1;

    ull acc2[8][4];
    #pragma unroll
    for (int i = 0; i < 8; i++)
        #pragma unroll
        for (int j = 0; j < 4; j++) acc2[i][j] = 0ull;

    for (int ch = 0; ch < NIT; ch++) {
        __syncthreads();           // buf[cur] ready; prior compute finished
        int cur = ch & 1, nxt = cur ^ 1;

        if (ch + 1 < NIT) {        // store prefetched chunk ch+1 -> buf[nxt]
            float* a = As[nxt]; float* bsm = Bs[nxt];
            a[(kc+0)*PA + mld] = ra0.x;  a[(kc+1)*PA + mld] = ra0.y;
            a[(kc+2)*PA + mld] = ra0.z;  a[(kc+3)*PA + mld] = ra0.w;
            a[(kc+0)*PA + 64 + mld] = ra1.x;  a[(kc+1)*PA + 64 + mld] = ra1.y;
            a[(kc+2)*PA + 64 + mld] = ra1.z;  a[(kc+3)*PA + 64 + mld] = ra1.w;
            bsm[(kc+0)*PA + mld] = rb0.x;  bsm[(kc+1)*PA + mld] = rb0.y;
            bsm[(kc+2)*PA + mld] = rb0.z;  bsm[(kc+3)*PA + mld] = rb0.w;
            bsm[(kc+0)*PA + 64 + mld] = rb1.x;  bsm[(kc+1)*PA + 64 + mld] = rb1.y;
            bsm[(kc+2)*PA + 64 + mld] = rb1.z;  bsm[(kc+3)*PA + 64 + mld] = rb1.w;
        }
        if (ch + 2 < NIT) {        // prefetch chunk ch+2
            pA0 += TK; pA1 += TK; pB0 += TK; pB1 += TK;
            ra0 = *(const float4*)pA0;  ra1 = *(const float4*)pA1;
            rb0 = *(const float4*)pB0;  rb1 = *(const float4*)pB1;
        }

        const float* a = As[cur]; const float* bsm = Bs[cur];
        #pragma unroll
        for (int k = 0; k < TK; k++) {
            float4 a0 = *(const float4*)&a[k*PA + ty*4];
            float4 a1 = *(const float4*)&a[k*PA + 64 + ty*4];
            ull aa[8] = {bcast2(a0.x), bcast2(a0.y), bcast2(a0.z), bcast2(a0.w),
                         bcast2(a1.x), bcast2(a1.y), bcast2(a1.z), bcast2(a1.w)};
            ulonglong2 bq0 = *(const ulonglong2*)&bsm[k*PA + tx*4];
            ulonglong2 bq1 = *(const ulonglong2*)&bsm[k*PA + 64 + tx*4];
            ull bp[4] = {bq0.x, bq0.y, bq1.x, bq1.y};
            #pragma unroll
            for (int i = 0; i < 8; i++)
                #pragma unroll
                for (int j = 0; j < 4; j++)
                    fma2(acc2[i][j], aa[i], bp[j]);
        }
    }

    float* E = g_epart + (((size_t)kchunk * 3 + s) * BATCH + b) * (CHAN * CHAN);
    #pragma unroll
    for (int i = 0; i < 8; i++) {
        int row = cBase + ((i < 4) ? (ty*4 + i) : (64 + ty*4 + i - 4));
        float2 c0 = unpack2(acc2[i][0]);
        float2 c1 = unpack2(acc2[i][1]);
        float2 c2 = unpack2(acc2[i][2]);
        float2 c3 = unpack2(acc2[i][3]);
        *(float4*)&E[(size_t)row * CHAN + dBase + tx*4] =
            make_float4(c0.x, c0.y, c1.x, c1.y);
        *(float4*)&E[(size_t)row * CHAN + dBase + 64 + tx*4] =
            make_float4(c2.x, c2.y, c3.x, c3.y);
    }
}

// ---------------------------------------------------------------------------
// Kernel 2: attn[b][c][:] = sum_s softmax(rowmax(E_s) - E_s), E_s = sum of
// KSPLIT partials. One warp per (b,c) row.
// ---------------------------------------------------------------------------
__global__ __launch_bounds__(256)
void softmax_sum_kernel()
{
    int gwarp = (blockIdx.x * blockDim.x + threadIdx.x) >> 5;
    int lane  = threadIdx.x & 31;

    float acc[8];
    #pragma unroll
    for (int i = 0; i < 8; i++) acc[i] = 0.f;

    #pragma unroll
    for (int s = 0; s < 3; s++) {
        float e[8];
        #pragma unroll
        for (int i = 0; i < 8; i++) e[i] = 0.f;
        #pragma unroll
        for (int p = 0; p < KSPLIT; p++) {
            const float* row = g_epart +
                (((size_t)p * 3 + s) * BATCH * CHAN + gwarp) * CHAN;
            float4 e0 = *(const float4*)&row[lane * 8];
            float4 e1 = *(const float4*)&row[lane * 8 + 4];
            e[0] += e0.x; e[1] += e0.y; e[2] += e0.z; e[3] += e0.w;
            e[4] += e1.x; e[5] += e1.y; e[6] += e1.z; e[7] += e1.w;
        }

        float m1 = e[0];
        #pragma unroll
        for (int i = 1; i < 8; i++) m1 = fmaxf(m1, e[i]);
        #pragma unroll
        for (int o = 16; o > 0; o >>= 1)
            m1 = fmaxf(m1, __shfl_xor_sync(0xffffffffu, m1, o));

        float v[8], m2 = -3.402823466e38f;
        #pragma unroll
        for (int i = 0; i < 8; i++) { v[i] = m1 - e[i]; m2 = fmaxf(m2, v[i]); }
        #pragma unroll
        for (int o = 16; o > 0; o >>= 1)
            m2 = fmaxf(m2, __shfl_xor_sync(0xffffffffu, m2, o));

        float p8[8], Ssum = 0.f;
        #pragma unroll
        for (int i = 0; i < 8; i++) { p8[i] = expf(v[i] - m2); Ssum += p8[i]; }
        #pragma unroll
        for (int o = 16; o > 0; o >>= 1)
            Ssum += __shfl_xor_sync(0xffffffffu, Ssum, o);

        float inv = 1.f / Ssum;
        #pragma unroll
        for (int i = 0; i < 8; i++) acc[i] += p8[i] * inv;
    }

    float* out = g_attn + (size_t)gwarp * CHAN + lane * 8;
    *(float4*)&out[0] = make_float4(acc[0], acc[1], acc[2], acc[3]);
    *(float4*)&out[4] = make_float4(acc[4], acc[5], acc[6], acc[7]);
}

// ---------------------------------------------------------------------------
// Kernels 3/4: TN GEMM, C = A @ B, K=256. Block tile 128x128x16, 8x8 micro,
// double-buffered smem (1 sync/iter), FFMA2 accumulators.
//   FINAL=false: O = gamma * acc
//   FINAL=true : O = acc + gamma*bias[m] + resid
// ---------------------------------------------------------------------------
template<int NCOLS, bool FINAL>
__global__ __launch_bounds__(256, 2)
void gemm_tn(const float* __restrict__ Ab, long aStride,
             const float* __restrict__ Bb, long bStride,
             float* __restrict__ Ob,
             const float* __restrict__ bias,
             const float* __restrict__ gamma_p,
             const float* __restrict__ resid)
{
    constexpr int TK = 16, Kdim = 256, PA = 136;
    constexpr int NIT = Kdim / TK;   // 16
    constexpr int NT = NCOLS / 128;
    __shared__ float As[2][TK * PA];
    __shared__ float Bs[2][TK * 128];

    int id = blockIdx.x;
    int nt = id % NT; id /= NT;
    int mt = id & 1;
    int b  = id >> 1;
    int mBase = mt * 128, nBase = nt * 128;

    const float* A = Ab + (size_t)b * aStride;
    const float* B = Bb + (size_t)b * bStride;
    float* O = Ob + (size_t)b * ((size_t)CHAN * NCOLS);
    const float* R = FINAL ? (resid + (size_t)b * ((size_t)CHAN * NCOLS)) : nullptr;

    int tid = threadIdx.x;
    int ty = tid >> 4, tx = tid & 15;

    int mldA = tid >> 2, kcA = (tid & 3) * 4;
    int krB = tid >> 5, nvB = tid & 31;

    const float* pA0 = A + (size_t)(mBase + mldA) * Kdim + kcA;
    const float* pA1 = pA0 + (size_t)64 * Kdim;
    const float* pB0 = B + (size_t)krB * NCOLS + nBase + nvB * 4;
    const float* pB1 = pB0 + (size_t)8 * NCOLS;

    float4 ra0, ra1, rb0, rb1;

    // prologue: chunk 0 -> buf 0
    ra0 = *(const float4*)pA0;  ra1 = *(const float4*)pA1;
    rb0 = *(const float4*)pB0;  rb1 = *(const float4*)pB1;
    {
        float* a = As[0]; float* bsm = Bs[0];
        a[(kcA+0)*PA + mldA] = ra0.x;  a[(kcA+1)*PA + mldA] = ra0.y;
        a[(kcA+2)*PA + mldA] = ra0.z;  a[(kcA+3)*PA + mldA] = ra0.w;
        a[(kcA+0)*PA + 64 + mldA] = ra1.x;  a[(kcA+1)*PA + 64 + mldA] = ra1.y;
        a[(kcA+2)*PA + 64 + mldA] = ra1.z;  a[(kcA+3)*PA + 64 + mldA] = ra1.w;
        *(float4*)&bsm[krB * 128 + nvB * 4]       = rb0;
        *(float4*)&bsm[(krB + 8) * 128 + nvB * 4] = rb1;
    }
    // prefetch chunk 1
    pA0 += TK; pA1 += TK;
    pB0 += (size_t)TK * NCOLS; pB1 += (size_t)TK * NCOLS;
    ra0 = *(const float4*)pA0;  ra1 = *(const float4*)pA1;
    rb0 = *(const float4*)pB0;  rb1 = *(const float4*)pB1;

    ull acc2[8][4];
    #pragma unroll
    for (int i = 0; i < 8; i++)
        #pragma unroll
        for (int j = 0; j < 4; j++) acc2[i][j] = 0ull;

    for (int ch = 0; ch < NIT; ch++) {
        __syncthreads();
        int cur = ch & 1, nxt = cur ^ 1;

        if (ch + 1 < NIT) {
            float* a = As[nxt]; float* bsm = Bs[nxt];
            a[(kcA+0)*PA + mldA] = ra0.x;  a[(kcA+1)*PA + mldA] = ra0.y;
            a[(kcA+2)*PA + mldA] = ra0.z;  a[(kcA+3)*PA + mldA] = ra0.w;
            a[(kcA+0)*PA + 64 + mldA] = ra1.x;  a[(kcA+1)*PA + 64 + mldA] = ra1.y;
            a[(kcA+2)*PA + 64 + mldA] = ra1.z;  a[(kcA+3)*PA + 64 + mldA] = ra1.w;
            *(float4*)&bsm[krB * 128 + nvB * 4]       = rb0;
            *(float4*)&bsm[(krB + 8) * 128 + nvB * 4] = rb1;
        }
        if (ch + 2 < NIT) {
            pA0 += TK; pA1 += TK;
            pB0 += (size_t)TK * NCOLS; pB1 += (size_t)TK * NCOLS;
            ra0 = *(const float4*)pA0;  ra1 = *(const float4*)pA1;
            rb0 = *(const float4*)pB0;  rb1 = *(const float4*)pB1;
        }

        const float* a = As[cur]; const float* bsm = Bs[cur];
        #pragma unroll
        for (int k = 0; k < TK; k++) {
            float4 a0 = *(const float4*)&a[k*PA + ty*4];
            float4 a1 = *(const float4*)&a[k*PA + 64 + ty*4];
            ull aa[8] = {bcast2(a0.x), bcast2(a0.y), bcast2(a0.z), bcast2(a0.w),
                         bcast2(a1.x), bcast2(a1.y), bcast2(a1.z), bcast2(a1.w)};
            ulonglong2 bq0 = *(const ulonglong2*)&bsm[k*128 + tx*4];
            ulonglong2 bq1 = *(const ulonglong2*)&bsm[k*128 + 64 + tx*4];
            ull bp[4] = {bq0.x, bq0.y, bq1.x, bq1.y};
            #pragma unroll
            for (int i = 0; i < 8; i++)
                #pragma unroll
                for (int j = 0; j < 4; j++)
                    fma2(acc2[i][j], aa[i], bp[j]);
        }
    }

    float gamma = gamma_p[0];
    #pragma unroll
    for (int i = 0; i < 8; i++) {
        int row = mBase + ((i < 4) ? (ty*4 + i) : (64 + ty*4 + i - 4));
        size_t base = (size_t)row * NCOLS + nBase + tx*4;
        float2 c0 = unpack2(acc2[i][0]);
        float2 c1 = unpack2(acc2[i][1]);
        float2 c2 = unpack2(acc2[i][2]);
        float2 c3 = unpack2(acc2[i][3]);
        if (FINAL) {
            float gb = gamma * bias[row];
            float4 r0 = *(const float4*)&R[base];
            float4 r1 = *(const float4*)&R[base + 64];
            *(float4*)&O[base] = make_float4(
                c0.x + gb + r0.x, c0.y + gb + r0.y,
                c1.x + gb + r0.z, c1.y + gb + r0.w);
            *(float4*)&O[base + 64] = make_float4(
                c2.x + gb + r1.x, c2.y + gb + r1.y,
                c3.x + gb + r1.z, c3.y + gb + r1.w);
        } else {
            *(float4*)&O[base] = make_float4(
                gamma*c0.x, gamma*c0.y, gamma*c1.x, gamma*c1.y);
            *(float4*)&O[base + 64] = make_float4(
                gamma*c2.x, gamma*c2.y, gamma*c3.x, gamma*c3.y);
        }
    }
}

// ---------------------------------------------------------------------------
extern "C" void kernel_launch(void* const* d_in, const int* in_sizes, int n_in,
                              void* d_out, int out_size)
{
    const float* x      = (const float*)d_in[0];
    const float* y      = (const float*)d_in[1];
    const float* z      = (const float*)d_in[2];
    const float* conv_w = (const float*)d_in[3];
    const float* conv_b = (const float*)d_in[4];
    const float* gamma  = (const float*)d_in[5];
    float* out = (float*)d_out;

    float *pAttn, *pM;
    cudaGetSymbolAddress((void**)&pAttn, g_attn);
    cudaGetSymbolAddress((void**)&pM, g_M);

    // 1) three energy GEMMs, split-K=4: 768 CTAs
    energy_kernel<<<3 * BATCH * 4 * KSPLIT, 256>>>(x, y, z);
    // 2) sum partials + softmax + sum over sources
    softmax_sum_kernel<<<BATCH * CHAN / 8, 256>>>();
    // 3) M_b = gamma * conv_w @ attn_b  (64 CTAs)
    gemm_tn<CHAN, false><<<BATCH * 2 * 2, 256>>>(
        conv_w, 0, pAttn, (long)CHAN * CHAN, pM, nullptr, gamma, nullptr);
    // 4) out = M_b @ x_b + gamma*conv_b + x  (1024 CTAs)
    gemm_tn<NPIX, true><<<BATCH * 2 * 32, 256>>>(
        pM, (long)CHAN * CHAN, x, (long)CHAN * NPIX, out, conv_b, gamma, x);
}

// round 13
// speedup vs baseline: 1.5455x; 1.1896x over previous
#include <cuda_runtime.h>
#include <math.h>
#include <stdint.h>

#define BATCH 16
#define CHAN  256
#define NPIX  4096
#define KSPLIT 4
#define KCH   (NPIX / KSPLIT)   // 1024

typedef unsigned long long ull;

// Scratch (allocation-free: __device__ globals)
__device__ float g_epart[(size_t)KSPLIT * 3 * BATCH * CHAN * CHAN];  // 50.3 MB
__device__ float g_attn[(unsigned)BATCH * CHAN * CHAN];
__device__ float g_M[(unsigned)BATCH * CHAN * CHAN];

// ---- packed f32x2 helpers ---------------------------------------------------
__device__ __forceinline__ ull bcast2(float v) {
    ull r; asm("mov.b64 %0, {%1, %1};" : "=l"(r) : "f"(v)); return r;
}
__device__ __forceinline__ void fma2(ull& d, ull a, ull b) {
    asm("fma.rn.f32x2 %0, %1, %2, %0;" : "+l"(d) : "l"(a), "l"(b));
}
__device__ __forceinline__ float2 unpack2(ull v) {
    float2 r; asm("mov.b64 {%0, %1}, %2;" : "=f"(r.x), "=f"(r.y) : "l"(v)); return r;
}

// ---------------------------------------------------------------------------
// Kernel 1: partial energy, split-K=4. Block tile 128x128x16, 128 threads,
// 16x8 micro-tile (2.67 FLOP/LDS-byte), double-buffered smem.
//   g_epart[kc][s][b][c][d] = sum_{n in chunk kc} x[b,c,n] * src_s[b,d,n]
// s=0 (x@x^T) is symmetric: tile (1,0) skipped, tile (0,1) writes its mirror.
// ---------------------------------------------------------------------------
__global__ __launch_bounds__(128, 2)
void energy_kernel(const float* __restrict__ x, const float* __restrict__ y,
                   const float* __restrict__ z)
{
    constexpr int TK = 16, PA = 136;
    constexpr int NIT = KCH / TK;     // 64
    __shared__ float As[2][TK * PA];
    __shared__ float Bs[2][TK * PA];

    int id = blockIdx.x;
    int t      = id & 3;
    int kchunk = (id >> 2) & 3;
    int bs     = id >> 4;
    int b  = bs & 15;
    int s  = bs >> 4;
    if (s == 0 && t == 2) return;           // symmetric: mirror of tile (0,1)
    int cBase = (t >> 1) * 128;
    int dBase = (t & 1) * 128;
    int kStart = kchunk * KCH;

    const float* A = x + (size_t)b * (CHAN * NPIX);
    const float* S = (s == 0 ? x : (s == 1 ? y : z)) + (size_t)b * (CHAN * NPIX);

    int tid = threadIdx.x;
    int tx = tid & 15, ty = tid >> 4;       // ty: m-block 0..7, tx: n-quad

    // loaders: thread owns gmem row (cBase+tid) of A and (dBase+tid) of S
    const float* pA = A + (size_t)(cBase + tid) * NPIX + kStart;
    const float* pB = S + (size_t)(dBase + tid) * NPIX + kStart;

    float4 ra[4], rb[4];
    #pragma unroll
    for (int g = 0; g < 4; g++) {
        ra[g] = *(const float4*)(pA + g * 4);
        rb[g] = *(const float4*)(pB + g * 4);
    }
    {   // chunk 0 -> buf 0  (transpose to [k][m])
        float* a = As[0]; float* bsm = Bs[0];
        #pragma unroll
        for (int g = 0; g < 4; g++) {
            a[(g*4+0)*PA + tid] = ra[g].x;  a[(g*4+1)*PA + tid] = ra[g].y;
            a[(g*4+2)*PA + tid] = ra[g].z;  a[(g*4+3)*PA + tid] = ra[g].w;
            bsm[(g*4+0)*PA + tid] = rb[g].x;  bsm[(g*4+1)*PA + tid] = rb[g].y;
            bsm[(g*4+2)*PA + tid] = rb[g].z;  bsm[(g*4+3)*PA + tid] = rb[g].w;
        }
    }
    pA += TK; pB += TK;
    #pragma unroll
    for (int g = 0; g < 4; g++) {
        ra[g] = *(const float4*)(pA + g * 4);
        rb[g] = *(const float4*)(pB + g * 4);
    }

    // acc2[q][n]: m-pair q (rows ty*16+2q, +2q+1) x col n
    // cols: n<4 -> dBase+tx*4+n ; n>=4 -> dBase+64+tx*4+(n-4)
    ull acc2[8][8];
    #pragma unroll
    for (int i = 0; i < 8; i++)
        #pragma unroll
        for (int j = 0; j < 8; j++) acc2[i][j] = 0ull;

    for (int ch = 0; ch < NIT; ch++) {
        __syncthreads();
        int cur = ch & 1, nxt = cur ^ 1;

        if (ch + 1 < NIT) {
            float* a = As[nxt]; float* bsm = Bs[nxt];
            #pragma unroll
            for (int g = 0; g < 4; g++) {
                a[(g*4+0)*PA + tid] = ra[g].x;  a[(g*4+1)*PA + tid] = ra[g].y;
                a[(g*4+2)*PA + tid] = ra[g].z;  a[(g*4+3)*PA + tid] = ra[g].w;
                bsm[(g*4+0)*PA + tid] = rb[g].x;  bsm[(g*4+1)*PA + tid] = rb[g].y;
                bsm[(g*4+2)*PA + tid] = rb[g].z;  bsm[(g*4+3)*PA + tid] = rb[g].w;
            }
        }
        if (ch + 2 < NIT) {
            pA += TK; pB += TK;
            #pragma unroll
            for (int g = 0; g < 4; g++) {
                ra[g] = *(const float4*)(pA + g * 4);
                rb[g] = *(const float4*)(pB + g * 4);
            }
        }

        const float* a = As[cur]; const float* bsm = Bs[cur];
        #pragma unroll
        for (int k = 0; k < TK; k++) {
            // 16 m-values = 8 packed pairs, straight from LDS.128 (no MOV)
            ulonglong2 q0 = *(const ulonglong2*)&a[k*PA + ty*16];
            ulonglong2 q1 = *(const ulonglong2*)&a[k*PA + ty*16 + 4];
            ulonglong2 q2 = *(const ulonglong2*)&a[k*PA + ty*16 + 8];
            ulonglong2 q3 = *(const ulonglong2*)&a[k*PA + ty*16 + 12];
            ull aa[8] = {q0.x, q0.y, q1.x, q1.y, q2.x, q2.y, q3.x, q3.y};
            float4 b0 = *(const float4*)&bsm[k*PA + tx*4];
            float4 b1 = *(const float4*)&bsm[k*PA + 64 + tx*4];
            ull bb[8] = {bcast2(b0.x), bcast2(b0.y), bcast2(b0.z), bcast2(b0.w),
                         bcast2(b1.x), bcast2(b1.y), bcast2(b1.z), bcast2(b1.w)};
            #pragma unroll
            for (int i = 0; i < 8; i++)
                #pragma unroll
                for (int j = 0; j < 8; j++)
                    fma2(acc2[i][j], aa[i], bb[j]);
        }
    }

    float* E = g_epart + (((size_t)kchunk * 3 + s) * BATCH + b) * (CHAN * CHAN);
    #pragma unroll
    for (int r = 0; r < 16; r++) {
        int row = cBase + ty * 16 + r;
        float v[8];
        #pragma unroll
        for (int n = 0; n < 8; n++) {
            float2 u = unpack2(acc2[r >> 1][n]);
            v[n] = (r & 1) ? u.y : u.x;
        }
        *(float4*)&E[(size_t)row * CHAN + dBase + tx*4] =
            make_float4(v[0], v[1], v[2], v[3]);
        *(float4*)&E[(size_t)row * CHAN + dBase + 64 + tx*4] =
            make_float4(v[4], v[5], v[6], v[7]);
    }

    // mirror write for the symmetric case (s=0, upper-right tile)
    if (s == 0 && t == 1) {
        #pragma unroll
        for (int n = 0; n < 8; n++) {
            int nGlob = dBase + ((n < 4) ? (tx*4 + n) : (64 + tx*4 + n - 4));
            float2 u0 = unpack2(acc2[0][n]), u1 = unpack2(acc2[1][n]);
            float2 u2 = unpack2(acc2[2][n]), u3 = unpack2(acc2[3][n]);
            float2 u4 = unpack2(acc2[4][n]), u5 = unpack2(acc2[5][n]);
            float2 u6 = unpack2(acc2[6][n]), u7 = unpack2(acc2[7][n]);
            float* dst = E + (size_t)nGlob * CHAN + cBase + ty * 16;
            *(float4*)(dst + 0)  = make_float4(u0.x, u0.y, u1.x, u1.y);
            *(float4*)(dst + 4)  = make_float4(u2.x, u2.y, u3.x, u3.y);
            *(float4*)(dst + 8)  = make_float4(u4.x, u4.y, u5.x, u5.y);
            *(float4*)(dst + 12) = make_float4(u6.x, u6.y, u7.x, u7.y);
        }
    }
}

// ---------------------------------------------------------------------------
// Kernel 2: attn[b][c][:] = sum_s softmax(rowmax(E_s) - E_s), E_s = sum of
// KSPLIT partials. One warp per (b,c) row.
// ---------------------------------------------------------------------------
__global__ __launch_bounds__(256)
void softmax_sum_kernel()
{
    int gwarp = (blockIdx.x * blockDim.x + threadIdx.x) >> 5;
    int lane  = threadIdx.x & 31;

    float acc[8];
    #pragma unroll
    for (int i = 0; i < 8; i++) acc[i] = 0.f;

    #pragma unroll
    for (int s = 0; s < 3; s++) {
        float e[8];
        #pragma unroll
        for (int i = 0; i < 8; i++) e[i] = 0.f;
        #pragma unroll
        for (int p = 0; p < KSPLIT; p++) {
            const float* row = g_epart +
                (((size_t)p * 3 + s) * BATCH * CHAN + gwarp) * CHAN;
            float4 e0 = *(const float4*)&row[lane * 8];
            float4 e1 = *(const float4*)&row[lane * 8 + 4];
            e[0] += e0.x; e[1] += e0.y; e[2] += e0.z; e[3] += e0.w;
            e[4] += e1.x; e[5] += e1.y; e[6] += e1.z; e[7] += e1.w;
        }

        float m1 = e[0];
        #pragma unroll
        for (int i = 1; i < 8; i++) m1 = fmaxf(m1, e[i]);
        #pragma unroll
        for (int o = 16; o > 0; o >>= 1)
            m1 = fmaxf(m1, __shfl_xor_sync(0xffffffffu, m1, o));

        float v[8], m2 = -3.402823466e38f;
        #pragma unroll
        for (int i = 0; i < 8; i++) { v[i] = m1 - e[i]; m2 = fmaxf(m2, v[i]); }
        #pragma unroll
        for (int o = 16; o > 0; o >>= 1)
            m2 = fmaxf(m2, __shfl_xor_sync(0xffffffffu, m2, o));

        float p8[8], Ssum = 0.f;
        #pragma unroll
        for (int i = 0; i < 8; i++) { p8[i] = expf(v[i] - m2); Ssum += p8[i]; }
        #pragma unroll
        for (int o = 16; o > 0; o >>= 1)
            Ssum += __shfl_xor_sync(0xffffffffu, Ssum, o);

        float inv = 1.f / Ssum;
        #pragma unroll
        for (int i = 0; i < 8; i++) acc[i] += p8[i] * inv;
    }

    float* out = g_attn + (size_t)gwarp * CHAN + lane * 8;
    *(float4*)&out[0] = make_float4(acc[0], acc[1], acc[2], acc[3]);
    *(float4*)&out[4] = make_float4(acc[4], acc[5], acc[6], acc[7]);
}

// ---------------------------------------------------------------------------
// Kernels 3/4: TN GEMM, C = A @ B, K=256. Block tile 128x128x16, 128 threads,
// 16x8 micro-tile, double-buffered smem.
//   FINAL=false: O = gamma * acc
//   FINAL=true : O = acc + gamma*bias[m] + resid
// ---------------------------------------------------------------------------
template<int NCOLS, bool FINAL>
__global__ __launch_bounds__(128, 2)
void gemm_tn(const float* __restrict__ Ab, long aStride,
             const float* __restrict__ Bb, long bStride,
             float* __restrict__ Ob,
             const float* __restrict__ bias,
             const float* __restrict__ gamma_p,
             const float* __restrict__ resid)
{
    constexpr int TK = 16, Kdim = 256, PA = 136;
    constexpr int NIT = Kdim / TK;   // 16
    constexpr int NT = NCOLS / 128;
    __shared__ float As[2][TK * PA];
    __shared__ float Bs[2][TK * 128];

    int id = blockIdx.x;
    int nt = id % NT; id /= NT;
    int mt = id & 1;
    int b  = id >> 1;
    int mBase = mt * 128, nBase = nt * 128;

    const float* A = Ab + (size_t)b * aStride;
    const float* B = Bb + (size_t)b * bStride;
    float* O = Ob + (size_t)b * ((size_t)CHAN * NCOLS);
    const float* R = FINAL ? (resid + (size_t)b * ((size_t)CHAN * NCOLS)) : nullptr;

    int tid = threadIdx.x;
    int tx = tid & 15, ty = tid >> 4;

    // A loader: thread owns row (mBase+tid), 16 k per chunk
    const float* pA = A + (size_t)(mBase + tid) * Kdim;
    // B loader: kr = tid>>5 (rows kr,kr+4,kr+8,kr+12), nv = tid&31 (col nv*4)
    int krB = tid >> 5, nvB = tid & 31;
    const float* pB = B + (size_t)krB * NCOLS + nBase + nvB * 4;

    float4 ra[4], rb[4];
    #pragma unroll
    for (int g = 0; g < 4; g++) {
        ra[g] = *(const float4*)(pA + g * 4);
        rb[g] = *(const float4*)(pB + (size_t)(g * 4) * NCOLS);
    }
    {
        float* a = As[0]; float* bsm = Bs[0];
        #pragma unroll
        for (int g = 0; g < 4; g++) {
            a[(g*4+0)*PA + tid] = ra[g].x;  a[(g*4+1)*PA + tid] = ra[g].y;
            a[(g*4+2)*PA + tid] = ra[g].z;  a[(g*4+3)*PA + tid] = ra[g].w;
            *(float4*)&bsm[(krB + g*4) * 128 + nvB * 4] = rb[g];
        }
    }
    pA += TK; pB += (size_t)TK * NCOLS;
    #pragma unroll
    for (int g = 0; g < 4; g++) {
        ra[g] = *(const float4*)(pA + g * 4);
        rb[g] = *(const float4*)(pB + (size_t)(g * 4) * NCOLS);
    }

    ull acc2[8][8];
    #pragma unroll
    for (int i = 0; i < 8; i++)
        #pragma unroll
        for (int j = 0; j < 8; j++) acc2[i][j] = 0ull;

    for (int ch = 0; ch < NIT; ch++) {
        __syncthreads();
        int cur = ch & 1, nxt = cur ^ 1;

        if (ch + 1 < NIT) {
            float* a = As[nxt]; float* bsm = Bs[nxt];
            #pragma unroll
            for (int g = 0; g < 4; g++) {
                a[(g*4+0)*PA + tid] = ra[g].x;  a[(g*4+1)*PA + tid] = ra[g].y;
                a[(g*4+2)*PA + tid] = ra[g].z;  a[(g*4+3)*PA + tid] = ra[g].w;
                *(float4*)&bsm[(krB + g*4) * 128 + nvB * 4] = rb[g];
            }
        }
        if (ch + 2 < NIT) {
            pA += TK; pB += (size_t)TK * NCOLS;
            #pragma unroll
            for (int g = 0; g < 4; g++) {
                ra[g] = *(const float4*)(pA + g * 4);
                rb[g] = *(const float4*)(pB + (size_t)(g * 4) * NCOLS);
            }
        }

        const float* a = As[cur]; const float* bsm = Bs[cur];
        #pragma unroll
        for (int k = 0; k < TK; k++) {
            ulonglong2 q0 = *(const ulonglong2*)&a[k*PA + ty*16];
            ulonglong2 q1 = *(const ulonglong2*)&a[k*PA + ty*16 + 4];
            ulonglong2 q2 = *(const ulonglong2*)&a[k*PA + ty*16 + 8];
            ulonglong2 q3 = *(const ulonglong2*)&a[k*PA + ty*16 + 12];
            ull aa[8] = {q0.x, q0.y, q1.x, q1.y, q2.x, q2.y, q3.x, q3.y};
            float4 b0 = *(const float4*)&bsm[k*128 + tx*4];
            float4 b1 = *(const float4*)&bsm[k*128 + 64 + tx*4];
            ull bb[8] = {bcast2(b0.x), bcast2(b0.y), bcast2(b0.z), bcast2(b0.w),
                         bcast2(b1.x), bcast2(b1.y), bcast2(b1.z), bcast2(b1.w)};
            #pragma unroll
            for (int i = 0; i < 8; i++)
                #pragma unroll
                for (int j = 0; j < 8; j++)
                    fma2(acc2[i][j], aa[i], bb[j]);
        }
    }

    float gamma = gamma_p[0];
    #pragma unroll
    for (int r = 0; r < 16; r++) {
        int row = mBase + ty * 16 + r;
        size_t base = (size_t)row * NCOLS + nBase + tx*4;
        float v[8];
        #pragma unroll
        for (int n = 0; n < 8; n++) {
            float2 u = unpack2(acc2[r >> 1][n]);
            v[n] = (r & 1) ? u.y : u.x;
        }
        if (FINAL) {
            float gb = gamma * bias[row];
            float4 r0 = *(const float4*)&R[base];
            float4 r1 = *(const float4*)&R[base + 64];
            *(float4*)&O[base] = make_float4(
                v[0] + gb + r0.x, v[1] + gb + r0.y,
                v[2] + gb + r0.z, v[3] + gb + r0.w);
            *(float4*)&O[base + 64] = make_float4(
                v[4] + gb + r1.x, v[5] + gb + r1.y,
                v[6] + gb + r1.z, v[7] + gb + r1.w);
        } else {
            *(float4*)&O[base] = make_float4(
                gamma*v[0], gamma*v[1], gamma*v[2], gamma*v[3]);
            *(float4*)&O[base + 64] = make_float4(
                gamma*v[4], gamma*v[5], gamma*v[6], gamma*v[7]);
        }
    }
}

// ---------------------------------------------------------------------------
extern "C" void kernel_launch(void* const* d_in, const int* in_sizes, int n_in,
                              void* d_out, int out_size)
{
    const float* x      = (const float*)d_in[0];
    const float* y      = (const float*)d_in[1];
    const float* z      = (const float*)d_in[2];
    const float* conv_w = (const float*)d_in[3];
    const float* conv_b = (const float*)d_in[4];
    const float* gamma  = (const float*)d_in[5];
    float* out = (float*)d_out;

    float *pAttn, *pM;
    cudaGetSymbolAddress((void**)&pAttn, g_attn);
    cudaGetSymbolAddress((void**)&pM, g_M);

    // 1) three energy GEMMs, split-K=4: 768 CTAs (64 exit early via symmetry)
    energy_kernel<<<3 * BATCH * 4 * KSPLIT, 128>>>(x, y, z);
    // 2) sum partials + softmax + sum over sources
    softmax_sum_kernel<<<BATCH * CHAN / 8, 256>>>();
    // 3) M_b = gamma * conv_w @ attn_b  (64 CTAs)
    gemm_tn<CHAN, false><<<BATCH * 2 * 2, 128>>>(
        conv_w, 0, pAttn, (long)CHAN * CHAN, pM, nullptr, gamma, nullptr);
    // 4) out = M_b @ x_b + gamma*conv_b + x  (1024 CTAs)
    gemm_tn<NPIX, true><<<BATCH * 2 * 32, 128>>>(
        pM, (long)CHAN * CHAN, x, (long)CHAN * NPIX, out, conv_b, gamma, x);
}